// round 6
// baseline (speedup 1.0000x reference)
#include <cuda_runtime.h>
#include <cstdint>

// Problem constants (fixed by the reference).
#define BB   4
#define DD   128
#define HH   128
#define WW   128
#define NMAX 500000
#define CIN  32
#define COUT 32
#define KVOL 125
#define GRID_SZ (BB * DD * HH * WW)   // 8,388,608
#define EPSV 1e-4f
#define FULLMASK 0xffffffffu

// -------- device scratch (allocation-free: static __device__ globals) --------
__device__ int   g_grid[GRID_SZ];          // flat voxel -> site row (-1 inactive)
__device__ int   g_flat[NMAX];             // packed flat index per site
__device__ float g_feat[(size_t)NMAX * CIN]; // normalized+ReLU features
__device__ float g_stats[2 * CIN];         // [sum(32), sumsq(32)]
__device__ float g_scale[CIN];
__device__ float g_bias[CIN];

// -------- kernel 1: reset grid to -1, zero out, zero stats --------
__global__ void k_reset(float* __restrict__ out, int outElems) {
    int i = blockIdx.x * blockDim.x + threadIdx.x;
    int stride = gridDim.x * blockDim.x;
    int4 m1 = make_int4(-1, -1, -1, -1);
    for (int e = i; e < GRID_SZ / 4; e += stride)
        reinterpret_cast<int4*>(g_grid)[e] = m1;
    float4 z4 = make_float4(0.f, 0.f, 0.f, 0.f);
    for (int e = i; e < outElems / 4; e += stride)
        reinterpret_cast<float4*>(out)[e] = z4;
    if (blockIdx.x == 0 && threadIdx.x < 2 * CIN)
        g_stats[threadIdx.x] = 0.f;
}

// -------- kernel 2: scatter site rows into the grid, pack coords --------
__global__ void k_scatter(const int* __restrict__ coords, int Nv) {
    int i = blockIdx.x * blockDim.x + threadIdx.x;
    if (i < Nv) {
        int4 c = reinterpret_cast<const int4*>(coords)[i];  // b, z, y, x
        int fl = (((c.x * DD + c.y) * HH + c.z) * WW) + c.w;
        g_grid[fl] = i;
        g_flat[i] = fl;
    }
}

// -------- kernel 3: per-channel sum / sumsq --------
__global__ void k_stats(const float* __restrict__ x, int Nv) {
    __shared__ float ss[8][33];
    __shared__ float ss2[8][33];
    int tid = threadIdx.x;
    int c = tid & 31;
    int wid = tid >> 5;
    float s = 0.f, s2 = 0.f;
    int total = Nv * CIN;
    int stride = gridDim.x * blockDim.x;  // multiple of 32 -> channel fixed
    for (int e = blockIdx.x * blockDim.x + tid; e < total; e += stride) {
        float v = x[e];
        s += v;
        s2 += v * v;
    }
    ss[wid][c] = s;
    ss2[wid][c] = s2;
    __syncthreads();
    if (tid < 32) {
        float a = 0.f, b = 0.f;
#pragma unroll
        for (int k = 0; k < 8; k++) { a += ss[k][tid]; b += ss2[k][tid]; }
        atomicAdd(&g_stats[tid], a);
        atomicAdd(&g_stats[32 + tid], b);
    }
}

// -------- kernel 4: fold BN into per-channel scale/bias --------
__global__ void k_finalize(const float* __restrict__ gamma,
                           const float* __restrict__ beta, int Nv) {
    int c = threadIdx.x;
    if (c < CIN) {
        float invN = 1.0f / (float)Nv;
        float mean = g_stats[c] * invN;
        float var = g_stats[32 + c] * invN - mean * mean;
        float sc = gamma[c] * rsqrtf(var + EPSV);
        g_scale[c] = sc;
        g_bias[c] = beta[c] - mean * sc;
    }
}

// -------- kernel 5: y = relu(x*scale + bias) --------
__global__ void k_norm(const float* __restrict__ x, int Nv) {
    int e = blockIdx.x * blockDim.x + threadIdx.x;  // float4 units
    int total = Nv * (CIN / 4);
    if (e < total) {
        float4 v = reinterpret_cast<const float4*>(x)[e];
        int c0 = (e * 4) & 31;
        float4 r;
        r.x = fmaxf(fmaf(v.x, g_scale[c0 + 0], g_bias[c0 + 0]), 0.f);
        r.y = fmaxf(fmaf(v.y, g_scale[c0 + 1], g_bias[c0 + 1]), 0.f);
        r.z = fmaxf(fmaf(v.z, g_scale[c0 + 2], g_bias[c0 + 2]), 0.f);
        r.w = fmaxf(fmaf(v.w, g_scale[c0 + 3], g_bias[c0 + 3]), 0.f);
        reinterpret_cast<float4*>(g_feat)[e] = r;
    }
}

// -------- kernel 6: sparse conv, one offset per blockIdx.y --------
// Each lane owns one output channel; the 32x32 weight of this offset lives in
// 32 registers per lane. Per active pair: 8 uniform LDG.128 broadcasts of the
// neighbor feature row + 32 FFMA + 1 fp32 RED into out.
__global__ void __launch_bounds__(256) k_conv(const float* __restrict__ weight,
                                              float* __restrict__ out, int Nv) {
    const int o = blockIdx.y;
    const int dz = o / 25 - 2;
    const int dy = (o / 5) % 5 - 2;
    const int dx = o % 5 - 2;
    const int lane = threadIdx.x & 31;

    // Weight column for this lane's cout: w[cin] = W[o][cin][lane]
    float w[CIN];
    const float* wp = weight + o * (CIN * COUT) + lane;
#pragma unroll
    for (int k = 0; k < CIN; k++) w[k] = __ldg(wp + k * COUT);

    int site = blockIdx.x * blockDim.x + threadIdx.x;
    int nidx = -1;
    if (site < Nv) {
        int fl = g_flat[site];
        int z = (fl >> 14) & 127;
        int y = (fl >> 7) & 127;
        int x = fl & 127;
        int nz = z + dz, ny = y + dy, nx = x + dx;
        if (((unsigned)nz < (unsigned)DD) & ((unsigned)ny < (unsigned)HH) &
            ((unsigned)nx < (unsigned)WW)) {
            nidx = g_grid[fl + dz * (HH * WW) + dy * WW + dx];
        }
    }

    unsigned mask = __ballot_sync(FULLMASK, nidx >= 0);
    const int base = blockIdx.x * blockDim.x + (threadIdx.x & ~31);
    while (mask) {
        int j = __ffs(mask) - 1;
        mask &= mask - 1;
        int n = __shfl_sync(FULLMASK, nidx, j);
        const float4* fp = reinterpret_cast<const float4*>(g_feat + (size_t)n * CIN);
        float acc = 0.f;
#pragma unroll
        for (int q = 0; q < 8; q++) {
            float4 f = __ldg(fp + q);
            acc = fmaf(f.x, w[4 * q + 0], acc);
            acc = fmaf(f.y, w[4 * q + 1], acc);
            acc = fmaf(f.z, w[4 * q + 2], acc);
            acc = fmaf(f.w, w[4 * q + 3], acc);
        }
        atomicAdd(out + (size_t)(base + j) * COUT + lane, acc);
    }
}

// -------- launch --------
extern "C" void kernel_launch(void* const* d_in, const int* in_sizes, int n_in,
                              void* d_out, int out_size) {
    const float* feats  = (const float*)d_in[0];   // [N, 32]
    const int*   coords = (const int*)d_in[1];     // [N, 4]
    const float* gamma  = (const float*)d_in[2];   // [32]
    const float* beta   = (const float*)d_in[3];   // [32]
    const float* weight = (const float*)d_in[4];   // [125, 32, 32]
    float* out = (float*)d_out;                    // [N, 32]

    int Nv = in_sizes[0] / CIN;
    if (Nv > NMAX) Nv = NMAX;

    k_reset<<<4096, 256>>>(out, Nv * CIN);
    k_scatter<<<(Nv + 255) / 256, 256>>>(coords, Nv);
    k_stats<<<1024, 256>>>(feats, Nv);
    k_finalize<<<1, 32>>>(gamma, beta, Nv);
    k_norm<<<(Nv * (CIN / 4) + 255) / 256, 256>>>(feats, Nv);

    dim3 gc((Nv + 255) / 256, KVOL);
    k_conv<<<gc, 256>>>(weight, out, Nv);
}